// round 11
// baseline (speedup 1.0000x reference)
#include <cuda_runtime.h>

#define TT   128   // timesteps
#define NN   32    // nodes
#define EE   512   // edges per timestep
#define INC  64    // input channels
#define HH   128   // hidden
#define SL   16    // seq len / windows per block
#define G4   512   // 4*HH gates
#define HP   18    // padded h row stride (floats)

// ---------------- device scratch (static, no allocs) ----------------
__device__ float g_hgcn  [TT * NN * HH];   // [t][n][h]
__device__ float g_P1    [NN * TT * G4];   // [n][t][j][4]  (gate-interleaved)
__device__ float g_WihTI1[NN * HH * G4];   // [n][k][j][4]
__device__ float g_WhhTI1[NN * HH * G4];
__device__ float g_WihTI2[NN * HH * G4];
__device__ float g_WhhTI2[NN * HH * G4];
__device__ float g_WfcT  [NN * HH * HH];   // [n][k][r]

// ---------------- helpers ----------------
__device__ __forceinline__ float sigf(float x) {
    return __fdividef(1.0f, 1.0f + __expf(-x));
}
__device__ __forceinline__ float tanhfast(float x) {
    x = fminf(fmaxf(x, -15.0f), 15.0f);
    float e = __expf(2.0f * x);
    return __fdividef(e - 1.0f, e + 1.0f);
}
__device__ __forceinline__ unsigned long long pk2(float a, float b) {
    unsigned long long r;
    asm("mov.b64 %0,{%1,%2};" : "=l"(r) : "f"(a), "f"(b));
    return r;
}
__device__ __forceinline__ void upk2(unsigned long long v, float& a, float& b) {
    asm("mov.b64 {%0,%1},%2;" : "=f"(a), "=f"(b) : "l"(v));
}
__device__ __forceinline__ void fma2(unsigned long long& d, unsigned long long a, unsigned long long b) {
    asm("fma.rn.f32x2 %0,%1,%2,%0;" : "+l"(d) : "l"(a), "l"(b));
}

// ================ fused prep: tik4 + fct + gcn ================
// block ranges:
//   [0, 2048)     tik4: transpose+gate-interleave 4 LSTM weight sets
//   [2048, 2560)  fct:  tiled transpose of Wfc
//   [2560, 2688)  gcn:  one timestep of the 2-layer GCN
#define PREP_TIK_END 2048
#define PREP_FCT_END 2560
#define PREP_NBLK    2688
#define GCN_SMEM_FLOATS (NN*HH + NN*HH + NN*NN + NN + NN + EE + EE)  // 10304

__global__ void __launch_bounds__(256) prep_kernel(
    const float* __restrict__ Wih1, const float* __restrict__ Whh1,
    const float* __restrict__ Wih2, const float* __restrict__ Whh2,
    const float* __restrict__ Wfc,
    const float* __restrict__ x, const int* __restrict__ ei,
    const float* __restrict__ W1, const float* __restrict__ b1,
    const float* __restrict__ W2, const float* __restrict__ b2)
{
    __shared__ __align__(16) float smb[GCN_SMEM_FLOATS];   // 41216 bytes
    int b = blockIdx.x, tid = threadIdx.x;

    if (b < PREP_TIK_END) {
        // ---- tik4: out[n][k][j*4+g] = in[n][g*128+j][k] ----
        float (*st)[32][33] = (float (*)[32][33])smb;
        int m   = b >> 9;            // 0..3 which weight matrix
        int rem = b & 511;
        int n   = rem >> 4;
        int yy  = rem & 15;
        int jt  = (yy >> 2) * 32;
        int kt  = (yy & 3) * 32;
        const float* srcs[4] = {Wih1, Whh1, Wih2, Whh2};
        float* dsts[4] = {g_WihTI1, g_WhhTI1, g_WihTI2, g_WhhTI2};
        const float* src = srcs[m] + (size_t)n * G4 * HH;
        float4* dst = (float4*)(dsts[m] + (size_t)n * HH * G4);
        int tx = tid & 31, ty = tid >> 5;
        #pragma unroll
        for (int g = 0; g < 4; g++)
            for (int jj = ty; jj < 32; jj += 8)
                st[g][jj][tx] = src[(g * HH + jt + jj) * HH + kt + tx];
        __syncthreads();
        for (int kk = ty; kk < 32; kk += 8) {
            float4 v;
            v.x = st[0][tx][kk]; v.y = st[1][tx][kk];
            v.z = st[2][tx][kk]; v.w = st[3][tx][kk];
            dst[(kt + kk) * HH + jt + tx] = v;
        }
    } else if (b < PREP_FCT_END) {
        // ---- fct: tiled transpose g_WfcT[n][k][r] = Wfc[n][r][k] ----
        float (*t)[33] = (float (*)[33])smb;
        int idx = b - PREP_TIK_END;
        int n  = idx >> 4;
        int yy = idx & 15;
        int tr = (yy >> 2) * 32;
        int tc = (yy & 3) * 32;
        const float* src = Wfc + (size_t)n * HH * HH;
        float* dst = g_WfcT + (size_t)n * HH * HH;
        int tx = tid & 31, ty = tid >> 5;
        #pragma unroll
        for (int i = ty; i < 32; i += 8)
            t[i][tx] = src[(tr + i) * HH + tc + tx];
        __syncthreads();
        #pragma unroll
        for (int i = ty; i < 32; i += 8)
            dst[(tc + i) * HH + tr + tx] = t[tx][i];
    } else {
        // ---- gcn: one timestep, dense-adjacency formulation ----
        float* A    = smb;                   // 4096 floats
        float* B    = A + NN * HH;           // 4096
        float* Adj  = B + NN * HH;           // 1024
        float* dinv = Adj + NN * NN;         // 32
        int*   deg  = (int*)(dinv + NN);     // 32
        int*   rowS = deg + NN;              // 512
        int*   colS = rowS + EE;             // 512

        int t = b - PREP_FCT_END;
        const int* rowp = ei + (size_t)t * 2 * EE;
        const int* colp = rowp + EE;

        if (tid < NN) deg[tid] = 1;                    // self-loop
        for (int i = tid; i < NN * NN; i += 256) Adj[i] = 0.0f;
        __syncthreads();
        for (int e = tid; e < EE; e += 256) {
            int r = rowp[e], c = colp[e];
            rowS[e] = r; colS[e] = c;
            atomicAdd(&deg[c], 1);
        }
        __syncthreads();
        if (tid < NN) dinv[tid] = rsqrtf((float)deg[tid]);
        __syncthreads();
        for (int e = tid; e < EE; e += 256) {
            int r = rowS[e], c = colS[e];
            atomicAdd(&Adj[c * NN + r], dinv[r] * dinv[c]);
        }
        if (tid < NN) atomicAdd(&Adj[tid * NN + tid], dinv[tid] * dinv[tid]);
        __syncthreads();

        // layer 1: A = x_t @ W1
        const float* xt = x + (size_t)t * NN * INC;
        for (int o = tid; o < NN * HH; o += 256) {
            int r = o >> 7, c = o & 127;
            float s = 0.0f;
            #pragma unroll 8
            for (int k = 0; k < INC; k++) s += xt[r * INC + k] * W1[k * HH + c];
            A[o] = s;
        }
        __syncthreads();
        // B = relu(Adj @ A + b1)
        for (int o = tid; o < NN * HH; o += 256) {
            int cn = o >> 7, ch = o & 127;
            float s = 0.0f;
            #pragma unroll
            for (int r = 0; r < NN; r++) s += Adj[cn * NN + r] * A[r * HH + ch];
            B[o] = fmaxf(s + b1[ch], 0.0f);
        }
        __syncthreads();
        // layer 2: A = B @ W2
        for (int o = tid; o < NN * HH; o += 256) {
            int r = o >> 7, c = o & 127;
            float s = 0.0f;
            #pragma unroll 8
            for (int k = 0; k < HH; k++) s += B[r * HH + k] * W2[k * HH + c];
            A[o] = s;
        }
        __syncthreads();
        // out = relu(Adj @ A + b2) -> global
        for (int o = tid; o < NN * HH; o += 256) {
            int cn = o >> 7, ch = o & 127;
            float s = 0.0f;
            #pragma unroll
            for (int r = 0; r < NN; r++) s += Adj[cn * NN + r] * A[r * HH + ch];
            g_hgcn[((size_t)t * NN + cn) * HH + ch] = fmaxf(s + b2[ch], 0.0f);
        }
    }
}

// ---------------- targets pass-through ----------------
__global__ void copy_y_kernel(const float* __restrict__ y, float* __restrict__ dst) {
    int i = blockIdx.x * 256 + threadIdx.x;
    if (i < TT * NN * 4) dst[i] = y[i];
}

// ---------------- precompute P1[n][t][j][4] = Wih1[n] @ h_gcn[t][n] ----------------
// grid (NN, 16): 8 timesteps per block; 256 threads = (j in 0..127, th in 0..1)
__global__ void __launch_bounds__(256) p1_kernel() {
    int n = blockIdx.x, tb = blockIdx.y * 8;
    __shared__ float hs[8][HH];
    int tid = threadIdx.x;
    for (int i = tid; i < 8 * HH; i += 256) {
        int tt = i >> 7, k = i & 127;
        hs[tt][k] = g_hgcn[((size_t)(tb + tt) * NN + n) * HH + k];
    }
    __syncthreads();
    int j = tid & 127, th = tid >> 7;
    const float4* Wp = (const float4*)(g_WihTI1 + (size_t)n * HH * G4);
    float4 acc[4];
    #pragma unroll
    for (int i = 0; i < 4; i++) acc[i] = make_float4(0.f, 0.f, 0.f, 0.f);
    float4 wvn = Wp[j];                          // prefetch k=0
    #pragma unroll 4
    for (int k = 0; k < HH; k++) {
        float4 wv = wvn;
        wvn = Wp[(((k + 1) & 127) << 7) + j];    // prefetch next (wraps harmlessly)
        #pragma unroll
        for (int i = 0; i < 4; i++) {
            float hv = hs[th * 4 + i][k];
            acc[i].x += wv.x * hv; acc[i].y += wv.y * hv;
            acc[i].z += wv.z * hv; acc[i].w += wv.w * hv;
        }
    }
    float4* out = (float4*)(g_P1 + (size_t)n * TT * G4);
    #pragma unroll
    for (int i = 0; i < 4; i++) out[(tb + th * 4 + i) * HH + j] = acc[i];
}

// ---------------- main 2-layer windowed LSTM + fc + heads (f32x2 packed) ----------------
// block = (node n, chunk of 16 windows), 128 threads: thread j owns hidden channel j.
// Windows packed in pairs (2w, 2w+1) into f32x2 lanes. Depth-1 rotating weight prefetch.
// (EXACT R6 version — known-good local optimum; do not touch.)
__global__ void __launch_bounds__(128) lstm_kernel(
    const float* __restrict__ bih1, const float* __restrict__ bhh1,
    const float* __restrict__ bih2, const float* __restrict__ bhh2,
    const float* __restrict__ bfc,
    const float* __restrict__ Wout0, const float* __restrict__ bout0,
    const float* __restrict__ Wout1, const float* __restrict__ bout1,
    float* __restrict__ dout)
{
    int n = blockIdx.x, chunk = blockIdx.y;
    int j = threadIdx.x;
    int tbase = chunk * SL;

    __shared__ __align__(16) float h1s[HH][HP];
    __shared__ __align__(16) float h2s[HH][HP];

    float c1[SL], c2[SL];
    #pragma unroll
    for (int w = 0; w < SL; w++) { c1[w] = 0.f; c2[w] = 0.f; }
    #pragma unroll
    for (int w2 = 0; w2 < 8; w2++) {
        ((unsigned long long*)h1s[j])[w2] = 0ull;
        ((unsigned long long*)h2s[j])[w2] = 0ull;
    }

    unsigned long long b1d[4], b2d[4];
    #pragma unroll
    for (int g = 0; g < 4; g++) {
        float v1 = bih1[n * G4 + g * HH + j] + bhh1[n * G4 + g * HH + j];
        float v2 = bih2[n * G4 + g * HH + j] + bhh2[n * G4 + g * HH + j];
        b1d[g] = pk2(v1, v1);
        b2d[g] = pk2(v2, v2);
    }

    const float4* Wh1 = (const float4*)(g_WhhTI1 + (size_t)n * HH * G4);
    const float4* Wi2 = (const float4*)(g_WihTI2 + (size_t)n * HH * G4);
    const float4* Wh2 = (const float4*)(g_WhhTI2 + (size_t)n * HH * G4);
    const float4* P1p = (const float4*)(g_P1     + (size_t)n * TT * G4);
    __syncthreads();

    for (int s = 0; s < SL; s++) {
        // ---- layer 1 gates: b1 + P1[ts] + Whh1 @ h1 ----
        unsigned long long acc[4][8];
        #pragma unroll
        for (int g = 0; g < 4; g++)
            #pragma unroll
            for (int w2 = 0; w2 < 8; w2++) acc[g][w2] = b1d[g];

        float4 wvn = Wh1[j];                         // prefetch k=0
        #pragma unroll 4
        for (int k = 0; k < HH; k++) {
            float4 wv = wvn;
            wvn = Wh1[(((k + 1) & 127) << 7) + j];   // prefetch next (wraps harmlessly)
            unsigned long long w0 = pk2(wv.x, wv.x), w1 = pk2(wv.y, wv.y);
            unsigned long long w2d = pk2(wv.z, wv.z), w3 = pk2(wv.w, wv.w);
            const unsigned long long* hp = (const unsigned long long*)h1s[k];
            #pragma unroll
            for (int w2 = 0; w2 < 8; w2++) {
                unsigned long long hv = hp[w2];
                fma2(acc[0][w2], w0, hv);
                fma2(acc[1][w2], w1, hv);
                fma2(acc[2][w2], w2d, hv);
                fma2(acc[3][w2], w3, hv);
            }
        }

        float hn[SL];
        #pragma unroll
        for (int w2 = 0; w2 < 8; w2++) {
            float i0, i1, f0, f1, g0, g1, o0, o1;
            upk2(acc[0][w2], i0, i1);
            upk2(acc[1][w2], f0, f1);
            upk2(acc[2][w2], g0, g1);
            upk2(acc[3][w2], o0, o1);
            int wA = 2 * w2, wB = wA + 1;
            int tsA = tbase + wA - (SL - 1) + s;
            int tsB = tsA + 1;
            if (tsA >= 0) {
                float4 p = P1p[tsA * HH + j];
                i0 += p.x; f0 += p.y; g0 += p.z; o0 += p.w;
            }
            if (tsB >= 0) {
                float4 p = P1p[tsB * HH + j];
                i1 += p.x; f1 += p.y; g1 += p.z; o1 += p.w;
            }
            c1[wA] = sigf(f0) * c1[wA] + sigf(i0) * tanhfast(g0);
            hn[wA] = sigf(o0) * tanhfast(c1[wA]);
            c1[wB] = sigf(f1) * c1[wB] + sigf(i1) * tanhfast(g1);
            hn[wB] = sigf(o1) * tanhfast(c1[wB]);
        }
        __syncthreads();
        #pragma unroll
        for (int w2 = 0; w2 < 8; w2++)
            ((unsigned long long*)h1s[j])[w2] = pk2(hn[2 * w2], hn[2 * w2 + 1]);
        __syncthreads();

        // ---- layer 2 gates: b2 + Wih2 @ h1new + Whh2 @ h2 ----
        #pragma unroll
        for (int g = 0; g < 4; g++)
            #pragma unroll
            for (int w2 = 0; w2 < 8; w2++) acc[g][w2] = b2d[g];

        float4 wivn = Wi2[j];                        // prefetch k=0
        float4 whvn = Wh2[j];
        #pragma unroll 2
        for (int k = 0; k < HH; k++) {
            float4 wiv = wivn;
            float4 whv = whvn;
            int kn = (((k + 1) & 127) << 7) + j;
            wivn = Wi2[kn];
            whvn = Wh2[kn];
            unsigned long long a0 = pk2(wiv.x, wiv.x), a1 = pk2(wiv.y, wiv.y);
            unsigned long long a2 = pk2(wiv.z, wiv.z), a3 = pk2(wiv.w, wiv.w);
            unsigned long long d0 = pk2(whv.x, whv.x), d1 = pk2(whv.y, whv.y);
            unsigned long long d2 = pk2(whv.z, whv.z), d3 = pk2(whv.w, whv.w);
            const unsigned long long* hp1 = (const unsigned long long*)h1s[k];
            const unsigned long long* hp2 = (const unsigned long long*)h2s[k];
            #pragma unroll
            for (int w2 = 0; w2 < 8; w2++) {
                unsigned long long hv1 = hp1[w2];
                unsigned long long hv2 = hp2[w2];
                fma2(acc[0][w2], a0, hv1); fma2(acc[0][w2], d0, hv2);
                fma2(acc[1][w2], a1, hv1); fma2(acc[1][w2], d1, hv2);
                fma2(acc[2][w2], a2, hv1); fma2(acc[2][w2], d2, hv2);
                fma2(acc[3][w2], a3, hv1); fma2(acc[3][w2], d3, hv2);
            }
        }

        #pragma unroll
        for (int w2 = 0; w2 < 8; w2++) {
            float i0, i1, f0, f1, g0, g1, o0, o1;
            upk2(acc[0][w2], i0, i1);
            upk2(acc[1][w2], f0, f1);
            upk2(acc[2][w2], g0, g1);
            upk2(acc[3][w2], o0, o1);
            int wA = 2 * w2, wB = wA + 1;
            c2[wA] = sigf(f0) * c2[wA] + sigf(i0) * tanhfast(g0);
            hn[wA] = sigf(o0) * tanhfast(c2[wA]);
            c2[wB] = sigf(f1) * c2[wB] + sigf(i1) * tanhfast(g1);
            hn[wB] = sigf(o1) * tanhfast(c2[wB]);
        }
        __syncthreads();
        #pragma unroll
        for (int w2 = 0; w2 < 8; w2++)
            ((unsigned long long*)h2s[j])[w2] = pk2(hn[2 * w2], hn[2 * w2 + 1]);
        __syncthreads();
    }

    // ---- last = relu(h2), fc = Wfc @ last + bfc ----
    #pragma unroll
    for (int w = 0; w < SL; w++) h1s[j][w] = fmaxf(h2s[j][w], 0.0f);
    __syncthreads();

    {
        float bb = bfc[n * HH + j];
        unsigned long long fcv[8];
        unsigned long long bbd = pk2(bb, bb);
        #pragma unroll
        for (int w2 = 0; w2 < 8; w2++) fcv[w2] = bbd;
        const float* Wf = g_WfcT + (size_t)n * HH * HH;
        #pragma unroll 4
        for (int k = 0; k < HH; k++) {
            float wf = Wf[k * HH + j];
            unsigned long long wfd = pk2(wf, wf);
            const unsigned long long* hr = (const unsigned long long*)h1s[k];
            #pragma unroll
            for (int w2 = 0; w2 < 8; w2++) fma2(fcv[w2], wfd, hr[w2]);
        }
        __syncthreads();
        #pragma unroll
        for (int w2 = 0; w2 < 8; w2++)
            ((unsigned long long*)h2s[j])[w2] = fcv[w2];
        __syncthreads();
    }

    // ---- heads: 16 windows x (4 + 2) outputs ----
    if (j < 96) {
        int w = j / 6, q = j % 6;
        const float* wr; float bo;
        if (q < 4) { wr = Wout0 + (size_t)(n * 4 + q) * HH;       bo = bout0[n * 4 + q]; }
        else       { wr = Wout1 + (size_t)(n * 2 + (q - 4)) * HH; bo = bout1[n * 2 + (q - 4)]; }
        float s2 = bo;
        #pragma unroll 8
        for (int k = 0; k < HH; k++) s2 += wr[k] * h2s[k][w];
        int t = tbase + w;
        if (q < 4) dout[((size_t)t * NN + n) * 4 + q] = s2;
        else       dout[(size_t)TT * NN * 4 + ((size_t)t * NN + n) * 2 + (q - 4)] = s2;
    }
}

// ---------------- launch ----------------
extern "C" void kernel_launch(void* const* d_in, const int* in_sizes, int n_in,
                              void* d_out, int out_size)
{
    const float* x     = (const float*)d_in[0];
    const int*   ei    = (const int*)  d_in[1];
    const float* y     = (const float*)d_in[3];
    const float* W1    = (const float*)d_in[4];
    const float* b1    = (const float*)d_in[5];
    const float* W2    = (const float*)d_in[6];
    const float* b2    = (const float*)d_in[7];
    const float* Wih1  = (const float*)d_in[8];
    const float* Whh1  = (const float*)d_in[9];
    const float* bih1  = (const float*)d_in[10];
    const float* bhh1  = (const float*)d_in[11];
    const float* Wih2  = (const float*)d_in[12];
    const float* Whh2  = (const float*)d_in[13];
    const float* bih2  = (const float*)d_in[14];
    const float* bhh2  = (const float*)d_in[15];
    const float* Wfc   = (const float*)d_in[16];
    const float* bfc   = (const float*)d_in[17];
    const float* Wout0 = (const float*)d_in[18];
    const float* bout0 = (const float*)d_in[19];
    const float* Wout1 = (const float*)d_in[20];
    const float* bout1 = (const float*)d_in[21];
    float* out = (float*)d_out;

    prep_kernel<<<PREP_NBLK, 256>>>(Wih1, Whh1, Wih2, Whh2, Wfc,
                                    x, ei, W1, b1, W2, b2);
    copy_y_kernel<<<(TT * NN * 4 + 255) / 256, 256>>>(y, out + (size_t)TT * NN * 4 + (size_t)TT * NN * 2);
    p1_kernel<<<dim3(NN, 16), 256>>>();
    lstm_kernel<<<dim3(NN, TT / SL), HH>>>(bih1, bhh1, bih2, bhh2, bfc,
                                           Wout0, bout0, Wout1, bout1, out);
}

// round 15
// speedup vs baseline: 1.5562x; 1.5562x over previous
#include <cuda_runtime.h>

#define TT   128   // timesteps
#define NN   32    // nodes
#define EE   512   // edges per timestep
#define INC  64    // input channels
#define HH   128   // hidden
#define SL   16    // seq len / windows per block
#define G4   512   // 4*HH gates
#define HP   18    // padded h row stride (floats)

// ---------------- device scratch (static, no allocs) ----------------
__device__ float g_hgcn  [TT * NN * HH];   // [t][n][h]
__device__ float g_P1    [NN * TT * G4];   // [n][t][j][4]  (gate-interleaved)
__device__ float g_WihTI1[NN * HH * G4];   // [n][k][j][4]
__device__ float g_WhhTI1[NN * HH * G4];
__device__ float g_WihTI2[NN * HH * G4];
__device__ float g_WhhTI2[NN * HH * G4];
__device__ float g_WfcT  [NN * HH * HH];   // [n][k][r]

// ---------------- helpers ----------------
__device__ __forceinline__ float sigf(float x) {
    return __fdividef(1.0f, 1.0f + __expf(-x));
}
__device__ __forceinline__ float tanhfast(float x) {
    x = fminf(fmaxf(x, -15.0f), 15.0f);
    float e = __expf(2.0f * x);
    return __fdividef(e - 1.0f, e + 1.0f);
}
__device__ __forceinline__ unsigned long long pk2(float a, float b) {
    unsigned long long r;
    asm("mov.b64 %0,{%1,%2};" : "=l"(r) : "f"(a), "f"(b));
    return r;
}
__device__ __forceinline__ void upk2(unsigned long long v, float& a, float& b) {
    asm("mov.b64 {%0,%1},%2;" : "=f"(a), "=f"(b) : "l"(v));
}
__device__ __forceinline__ void fma2(unsigned long long& d, unsigned long long a, unsigned long long b) {
    asm("fma.rn.f32x2 %0,%1,%2,%0;" : "+l"(d) : "l"(a), "l"(b));
}

// ================ fused prep: tik4 + fct + gcn ================
#define PREP_TIK_END 2048
#define PREP_FCT_END 2560
#define PREP_NBLK    2688
#define GCN_SMEM_FLOATS (NN*HH + NN*HH + NN*NN + NN + NN + EE + EE)  // 10304

__global__ void __launch_bounds__(256) prep_kernel(
    const float* __restrict__ Wih1, const float* __restrict__ Whh1,
    const float* __restrict__ Wih2, const float* __restrict__ Whh2,
    const float* __restrict__ Wfc,
    const float* __restrict__ x, const int* __restrict__ ei,
    const float* __restrict__ W1, const float* __restrict__ b1,
    const float* __restrict__ W2, const float* __restrict__ b2)
{
    __shared__ __align__(16) float smb[GCN_SMEM_FLOATS];
    int b = blockIdx.x, tid = threadIdx.x;

    if (b < PREP_TIK_END) {
        // ---- tik4: out[n][k][j*4+g] = in[n][g*128+j][k] ----
        float (*st)[32][33] = (float (*)[32][33])smb;
        int m   = b >> 9;
        int rem = b & 511;
        int n   = rem >> 4;
        int yy  = rem & 15;
        int jt  = (yy >> 2) * 32;
        int kt  = (yy & 3) * 32;
        const float* srcs[4] = {Wih1, Whh1, Wih2, Whh2};
        float* dsts[4] = {g_WihTI1, g_WhhTI1, g_WihTI2, g_WhhTI2};
        const float* src = srcs[m] + (size_t)n * G4 * HH;
        float4* dst = (float4*)(dsts[m] + (size_t)n * HH * G4);
        int tx = tid & 31, ty = tid >> 5;
        #pragma unroll
        for (int g = 0; g < 4; g++)
            for (int jj = ty; jj < 32; jj += 8)
                st[g][jj][tx] = src[(g * HH + jt + jj) * HH + kt + tx];
        __syncthreads();
        for (int kk = ty; kk < 32; kk += 8) {
            float4 v;
            v.x = st[0][tx][kk]; v.y = st[1][tx][kk];
            v.z = st[2][tx][kk]; v.w = st[3][tx][kk];
            dst[(kt + kk) * HH + jt + tx] = v;
        }
    } else if (b < PREP_FCT_END) {
        // ---- fct: tiled transpose g_WfcT[n][k][r] = Wfc[n][r][k] ----
        float (*t)[33] = (float (*)[33])smb;
        int idx = b - PREP_TIK_END;
        int n  = idx >> 4;
        int yy = idx & 15;
        int tr = (yy >> 2) * 32;
        int tc = (yy & 3) * 32;
        const float* src = Wfc + (size_t)n * HH * HH;
        float* dst = g_WfcT + (size_t)n * HH * HH;
        int tx = tid & 31, ty = tid >> 5;
        #pragma unroll
        for (int i = ty; i < 32; i += 8)
            t[i][tx] = src[(tr + i) * HH + tc + tx];
        __syncthreads();
        #pragma unroll
        for (int i = ty; i < 32; i += 8)
            dst[(tc + i) * HH + tr + tx] = t[tx][i];
    } else {
        // ---- gcn: one timestep, dense-adjacency formulation ----
        float* A    = smb;
        float* B    = A + NN * HH;
        float* Adj  = B + NN * HH;
        float* dinv = Adj + NN * NN;
        int*   deg  = (int*)(dinv + NN);
        int*   rowS = deg + NN;
        int*   colS = rowS + EE;

        int t = b - PREP_FCT_END;
        const int* rowp = ei + (size_t)t * 2 * EE;
        const int* colp = rowp + EE;

        if (tid < NN) deg[tid] = 1;
        for (int i = tid; i < NN * NN; i += 256) Adj[i] = 0.0f;
        __syncthreads();
        for (int e = tid; e < EE; e += 256) {
            int r = rowp[e], c = colp[e];
            rowS[e] = r; colS[e] = c;
            atomicAdd(&deg[c], 1);
        }
        __syncthreads();
        if (tid < NN) dinv[tid] = rsqrtf((float)deg[tid]);
        __syncthreads();
        for (int e = tid; e < EE; e += 256) {
            int r = rowS[e], c = colS[e];
            atomicAdd(&Adj[c * NN + r], dinv[r] * dinv[c]);
        }
        if (tid < NN) atomicAdd(&Adj[tid * NN + tid], dinv[tid] * dinv[tid]);
        __syncthreads();

        const float* xt = x + (size_t)t * NN * INC;
        for (int o = tid; o < NN * HH; o += 256) {
            int r = o >> 7, c = o & 127;
            float s = 0.0f;
            #pragma unroll 8
            for (int k = 0; k < INC; k++) s += xt[r * INC + k] * W1[k * HH + c];
            A[o] = s;
        }
        __syncthreads();
        for (int o = tid; o < NN * HH; o += 256) {
            int cn = o >> 7, ch = o & 127;
            float s = 0.0f;
            #pragma unroll
            for (int r = 0; r < NN; r++) s += Adj[cn * NN + r] * A[r * HH + ch];
            B[o] = fmaxf(s + b1[ch], 0.0f);
        }
        __syncthreads();
        for (int o = tid; o < NN * HH; o += 256) {
            int r = o >> 7, c = o & 127;
            float s = 0.0f;
            #pragma unroll 8
            for (int k = 0; k < HH; k++) s += B[r * HH + k] * W2[k * HH + c];
            A[o] = s;
        }
        __syncthreads();
        for (int o = tid; o < NN * HH; o += 256) {
            int cn = o >> 7, ch = o & 127;
            float s = 0.0f;
            #pragma unroll
            for (int r = 0; r < NN; r++) s += Adj[cn * NN + r] * A[r * HH + ch];
            g_hgcn[((size_t)t * NN + cn) * HH + ch] = fmaxf(s + b2[ch], 0.0f);
        }
    }
}

// ---------------- targets pass-through ----------------
__global__ void copy_y_kernel(const float* __restrict__ y, float* __restrict__ dst) {
    int i = blockIdx.x * 256 + threadIdx.x;
    if (i < TT * NN * 4) dst[i] = y[i];
}

// ---------------- precompute P1[n][t][j][4] = Wih1[n] @ h_gcn[t][n] ----------------
__global__ void __launch_bounds__(256) p1_kernel() {
    int n = blockIdx.x, tb = blockIdx.y * 8;
    __shared__ float hs[8][HH];
    int tid = threadIdx.x;
    for (int i = tid; i < 8 * HH; i += 256) {
        int tt = i >> 7, k = i & 127;
        hs[tt][k] = g_hgcn[((size_t)(tb + tt) * NN + n) * HH + k];
    }
    __syncthreads();
    int j = tid & 127, th = tid >> 7;
    const float4* Wp = (const float4*)(g_WihTI1 + (size_t)n * HH * G4);
    float4 acc[4];
    #pragma unroll
    for (int i = 0; i < 4; i++) acc[i] = make_float4(0.f, 0.f, 0.f, 0.f);
    float4 wvn = Wp[j];
    #pragma unroll 4
    for (int k = 0; k < HH; k++) {
        float4 wv = wvn;
        wvn = Wp[(((k + 1) & 127) << 7) + j];
        #pragma unroll
        for (int i = 0; i < 4; i++) {
            float hv = hs[th * 4 + i][k];
            acc[i].x += wv.x * hv; acc[i].y += wv.y * hv;
            acc[i].z += wv.z * hv; acc[i].w += wv.w * hv;
        }
    }
    float4* out = (float4*)(g_P1 + (size_t)n * TT * G4);
    #pragma unroll
    for (int i = 0; i < 4; i++) out[(tb + th * 4 + i) * HH + j] = acc[i];
}

// ---------------- main 2-layer windowed LSTM + fc + heads (f32x2 packed) ----------------
// R6 hot loops, but h1/h2 double-buffered -> ONE __syncthreads per step.
// Hazard analysis: L1 reads h1[rb], writes h1[wb]; SYNC; L2 reads h1[wb]+h2[rb], writes h2[wb].
// Every write targets the buffer whose last readers were separated by an intervening barrier.
__global__ void __launch_bounds__(128) lstm_kernel(
    const float* __restrict__ bih1, const float* __restrict__ bhh1,
    const float* __restrict__ bih2, const float* __restrict__ bhh2,
    const float* __restrict__ bfc,
    const float* __restrict__ Wout0, const float* __restrict__ bout0,
    const float* __restrict__ Wout1, const float* __restrict__ bout1,
    float* __restrict__ dout)
{
    int n = blockIdx.x, chunk = blockIdx.y;
    int j = threadIdx.x;
    int tbase = chunk * SL;

    __shared__ __align__(16) float h1s[2][HH][HP];
    __shared__ __align__(16) float h2s[2][HH][HP];

    float c1[SL], c2[SL];
    #pragma unroll
    for (int w = 0; w < SL; w++) { c1[w] = 0.f; c2[w] = 0.f; }
    #pragma unroll
    for (int w2 = 0; w2 < 8; w2++) {
        ((unsigned long long*)h1s[0][j])[w2] = 0ull;
        ((unsigned long long*)h2s[0][j])[w2] = 0ull;
    }

    unsigned long long b1d[4], b2d[4];
    #pragma unroll
    for (int g = 0; g < 4; g++) {
        float v1 = bih1[n * G4 + g * HH + j] + bhh1[n * G4 + g * HH + j];
        float v2 = bih2[n * G4 + g * HH + j] + bhh2[n * G4 + g * HH + j];
        b1d[g] = pk2(v1, v1);
        b2d[g] = pk2(v2, v2);
    }

    const float4* Wh1 = (const float4*)(g_WhhTI1 + (size_t)n * HH * G4);
    const float4* Wi2 = (const float4*)(g_WihTI2 + (size_t)n * HH * G4);
    const float4* Wh2 = (const float4*)(g_WhhTI2 + (size_t)n * HH * G4);
    const float4* P1p = (const float4*)(g_P1     + (size_t)n * TT * G4);
    __syncthreads();

    for (int s = 0; s < SL; s++) {
        int rb = s & 1, wb = rb ^ 1;
        float (*h1R)[HP] = h1s[rb];
        float (*h1W)[HP] = h1s[wb];
        float (*h2R)[HP] = h2s[rb];
        float (*h2W)[HP] = h2s[wb];

        // ---- layer 1 gates: b1 + P1[ts] + Whh1 @ h1[rb] ----
        unsigned long long acc[4][8];
        #pragma unroll
        for (int g = 0; g < 4; g++)
            #pragma unroll
            for (int w2 = 0; w2 < 8; w2++) acc[g][w2] = b1d[g];

        float4 wvn = Wh1[j];
        #pragma unroll 4
        for (int k = 0; k < HH; k++) {
            float4 wv = wvn;
            wvn = Wh1[(((k + 1) & 127) << 7) + j];
            unsigned long long w0 = pk2(wv.x, wv.x), w1 = pk2(wv.y, wv.y);
            unsigned long long w2d = pk2(wv.z, wv.z), w3 = pk2(wv.w, wv.w);
            const unsigned long long* hp = (const unsigned long long*)h1R[k];
            #pragma unroll
            for (int w2 = 0; w2 < 8; w2++) {
                unsigned long long hv = hp[w2];
                fma2(acc[0][w2], w0, hv);
                fma2(acc[1][w2], w1, hv);
                fma2(acc[2][w2], w2d, hv);
                fma2(acc[3][w2], w3, hv);
            }
        }

        #pragma unroll
        for (int w2 = 0; w2 < 8; w2++) {
            float i0, i1, f0, f1, g0, g1, o0, o1;
            upk2(acc[0][w2], i0, i1);
            upk2(acc[1][w2], f0, f1);
            upk2(acc[2][w2], g0, g1);
            upk2(acc[3][w2], o0, o1);
            int wA = 2 * w2, wB = wA + 1;
            int tsA = tbase + wA - (SL - 1) + s;
            int tsB = tsA + 1;
            if (tsA >= 0) {
                float4 p = P1p[tsA * HH + j];
                i0 += p.x; f0 += p.y; g0 += p.z; o0 += p.w;
            }
            if (tsB >= 0) {
                float4 p = P1p[tsB * HH + j];
                i1 += p.x; f1 += p.y; g1 += p.z; o1 += p.w;
            }
            c1[wA] = sigf(f0) * c1[wA] + sigf(i0) * tanhfast(g0);
            float hA = sigf(o0) * tanhfast(c1[wA]);
            c1[wB] = sigf(f1) * c1[wB] + sigf(i1) * tanhfast(g1);
            float hB = sigf(o1) * tanhfast(c1[wB]);
            ((unsigned long long*)h1W[j])[w2] = pk2(hA, hB);
        }
        __syncthreads();   // the ONE barrier per step

        // ---- layer 2 gates: b2 + Wih2 @ h1[wb] + Whh2 @ h2[rb] ----
        #pragma unroll
        for (int g = 0; g < 4; g++)
            #pragma unroll
            for (int w2 = 0; w2 < 8; w2++) acc[g][w2] = b2d[g];

        float4 wivn = Wi2[j];
        float4 whvn = Wh2[j];
        #pragma unroll 2
        for (int k = 0; k < HH; k++) {
            float4 wiv = wivn;
            float4 whv = whvn;
            int kn = (((k + 1) & 127) << 7) + j;
            wivn = Wi2[kn];
            whvn = Wh2[kn];
            unsigned long long a0 = pk2(wiv.x, wiv.x), a1 = pk2(wiv.y, wiv.y);
            unsigned long long a2 = pk2(wiv.z, wiv.z), a3 = pk2(wiv.w, wiv.w);
            unsigned long long d0 = pk2(whv.x, whv.x), d1 = pk2(whv.y, whv.y);
            unsigned long long d2 = pk2(whv.z, whv.z), d3 = pk2(whv.w, whv.w);
            const unsigned long long* hp1 = (const unsigned long long*)h1W[k];
            const unsigned long long* hp2 = (const unsigned long long*)h2R[k];
            #pragma unroll
            for (int w2 = 0; w2 < 8; w2++) {
                unsigned long long hv1 = hp1[w2];
                unsigned long long hv2 = hp2[w2];
                fma2(acc[0][w2], a0, hv1); fma2(acc[0][w2], d0, hv2);
                fma2(acc[1][w2], a1, hv1); fma2(acc[1][w2], d1, hv2);
                fma2(acc[2][w2], a2, hv1); fma2(acc[2][w2], d2, hv2);
                fma2(acc[3][w2], a3, hv1); fma2(acc[3][w2], d3, hv2);
            }
        }

        #pragma unroll
        for (int w2 = 0; w2 < 8; w2++) {
            float i0, i1, f0, f1, g0, g1, o0, o1;
            upk2(acc[0][w2], i0, i1);
            upk2(acc[1][w2], f0, f1);
            upk2(acc[2][w2], g0, g1);
            upk2(acc[3][w2], o0, o1);
            int wA = 2 * w2, wB = wA + 1;
            c2[wA] = sigf(f0) * c2[wA] + sigf(i0) * tanhfast(g0);
            float hA = sigf(o0) * tanhfast(c2[wA]);
            c2[wB] = sigf(f1) * c2[wB] + sigf(i1) * tanhfast(g1);
            float hB = sigf(o1) * tanhfast(c2[wB]);
            ((unsigned long long*)h2W[j])[w2] = pk2(hA, hB);
        }
        // no trailing barrier: next step's single barrier separates all hazards
    }

    // final h2 lives in buffer (15&1)^1 = 0. Thread j reads ONLY its own row -> no sync needed.
    #pragma unroll
    for (int w = 0; w < SL; w++) h1s[0][j][w] = fmaxf(h2s[0][j][w], 0.0f);
    __syncthreads();

    {
        float bb = bfc[n * HH + j];
        unsigned long long fcv[8];
        unsigned long long bbd = pk2(bb, bb);
        #pragma unroll
        for (int w2 = 0; w2 < 8; w2++) fcv[w2] = bbd;
        const float* Wf = g_WfcT + (size_t)n * HH * HH;
        #pragma unroll 4
        for (int k = 0; k < HH; k++) {
            float wf = Wf[k * HH + j];
            unsigned long long wfd = pk2(wf, wf);
            const unsigned long long* hr = (const unsigned long long*)h1s[0][k];
            #pragma unroll
            for (int w2 = 0; w2 < 8; w2++) fma2(fcv[w2], wfd, hr[w2]);
        }
        __syncthreads();
        #pragma unroll
        for (int w2 = 0; w2 < 8; w2++)
            ((unsigned long long*)h2s[0][j])[w2] = fcv[w2];
        __syncthreads();
    }

    // ---- heads: 16 windows x (4 + 2) outputs ----
    if (j < 96) {
        int w = j / 6, q = j % 6;
        const float* wr; float bo;
        if (q < 4) { wr = Wout0 + (size_t)(n * 4 + q) * HH;       bo = bout0[n * 4 + q]; }
        else       { wr = Wout1 + (size_t)(n * 2 + (q - 4)) * HH; bo = bout1[n * 2 + (q - 4)]; }
        float s2 = bo;
        #pragma unroll 8
        for (int k = 0; k < HH; k++) s2 += wr[k] * h2s[0][k][w];
        int t = tbase + w;
        if (q < 4) dout[((size_t)t * NN + n) * 4 + q] = s2;
        else       dout[(size_t)TT * NN * 4 + ((size_t)t * NN + n) * 2 + (q - 4)] = s2;
    }
}

// ---------------- launch ----------------
extern "C" void kernel_launch(void* const* d_in, const int* in_sizes, int n_in,
                              void* d_out, int out_size)
{
    const float* x     = (const float*)d_in[0];
    const int*   ei    = (const int*)  d_in[1];
    const float* y     = (const float*)d_in[3];
    const float* W1    = (const float*)d_in[4];
    const float* b1    = (const float*)d_in[5];
    const float* W2    = (const float*)d_in[6];
    const float* b2    = (const float*)d_in[7];
    const float* Wih1  = (const float*)d_in[8];
    const float* Whh1  = (const float*)d_in[9];
    const float* bih1  = (const float*)d_in[10];
    const float* bhh1  = (const float*)d_in[11];
    const float* Wih2  = (const float*)d_in[12];
    const float* Whh2  = (const float*)d_in[13];
    const float* bih2  = (const float*)d_in[14];
    const float* bhh2  = (const float*)d_in[15];
    const float* Wfc   = (const float*)d_in[16];
    const float* bfc   = (const float*)d_in[17];
    const float* Wout0 = (const float*)d_in[18];
    const float* bout0 = (const float*)d_in[19];
    const float* Wout1 = (const float*)d_in[20];
    const float* bout1 = (const float*)d_in[21];
    float* out = (float*)d_out;

    prep_kernel<<<PREP_NBLK, 256>>>(Wih1, Whh1, Wih2, Whh2, Wfc,
                                    x, ei, W1, b1, W2, b2);
    copy_y_kernel<<<(TT * NN * 4 + 255) / 256, 256>>>(y, out + (size_t)TT * NN * 4 + (size_t)TT * NN * 2);
    p1_kernel<<<dim3(NN, 16), 256>>>();
    lstm_kernel<<<dim3(NN, TT / SL), HH>>>(bih1, bhh1, bih2, bhh2, bfc,
                                           Wout0, bout0, Wout1, bout1, out);
}

// round 16
// speedup vs baseline: 1.5648x; 1.0055x over previous
#include <cuda_runtime.h>

#define TT   128   // timesteps
#define NN   32    // nodes
#define EE   512   // edges per timestep
#define INC  64    // input channels
#define HH   128   // hidden
#define SL   16    // seq len / windows per block
#define G4   512   // 4*HH gates
#define HP   18    // padded h row stride (floats)

// ---------------- device scratch (static, no allocs) ----------------
__device__ float g_hgcn  [TT * NN * HH];   // [t][n][h]
__device__ float g_P1    [NN * TT * G4];   // [n][t][j][4]  (gate-interleaved)
__device__ float g_WihTI1[NN * HH * G4];   // [n][k][j][4]
__device__ float g_WhhTI1[NN * HH * G4];
__device__ float g_WihTI2[NN * HH * G4];
__device__ float g_WhhTI2[NN * HH * G4];
__device__ float g_WfcT  [NN * HH * HH];   // [n][k][r]

// ---------------- helpers ----------------
__device__ __forceinline__ float sigf(float x) {
    return __fdividef(1.0f, 1.0f + __expf(-x));
}
__device__ __forceinline__ float tanhfast(float x) {
    x = fminf(fmaxf(x, -15.0f), 15.0f);
    float e = __expf(2.0f * x);
    return __fdividef(e - 1.0f, e + 1.0f);
}
__device__ __forceinline__ unsigned long long pk2(float a, float b) {
    unsigned long long r;
    asm("mov.b64 %0,{%1,%2};" : "=l"(r) : "f"(a), "f"(b));
    return r;
}
__device__ __forceinline__ void upk2(unsigned long long v, float& a, float& b) {
    asm("mov.b64 {%0,%1},%2;" : "=f"(a), "=f"(b) : "l"(v));
}
__device__ __forceinline__ void fma2(unsigned long long& d, unsigned long long a, unsigned long long b) {
    asm("fma.rn.f32x2 %0,%1,%2,%0;" : "+l"(d) : "l"(a), "l"(b));
}

// ================ fused prep: tik4 + fct + gcn + copy_y ================
#define PREP_TIK_END 2048
#define PREP_FCT_END 2560
#define PREP_GCN_END 2688
#define PREP_NBLK    2752
#define GCN_SMEM_FLOATS (NN*HH + NN*HH + NN*NN + NN + NN + EE + EE)  // 10304

__global__ void __launch_bounds__(256) prep_kernel(
    const float* __restrict__ Wih1, const float* __restrict__ Whh1,
    const float* __restrict__ Wih2, const float* __restrict__ Whh2,
    const float* __restrict__ Wfc,
    const float* __restrict__ x, const int* __restrict__ ei,
    const float* __restrict__ W1, const float* __restrict__ b1,
    const float* __restrict__ W2, const float* __restrict__ b2,
    const float* __restrict__ y, float* __restrict__ ydst)
{
    __shared__ __align__(16) float smb[GCN_SMEM_FLOATS];
    int b = blockIdx.x, tid = threadIdx.x;

    if (b < PREP_TIK_END) {
        // ---- tik4: out[n][k][j*4+g] = in[n][g*128+j][k] ----
        float (*st)[32][33] = (float (*)[32][33])smb;
        int m   = b >> 9;
        int rem = b & 511;
        int n   = rem >> 4;
        int yy  = rem & 15;
        int jt  = (yy >> 2) * 32;
        int kt  = (yy & 3) * 32;
        const float* srcs[4] = {Wih1, Whh1, Wih2, Whh2};
        float* dsts[4] = {g_WihTI1, g_WhhTI1, g_WihTI2, g_WhhTI2};
        const float* src = srcs[m] + (size_t)n * G4 * HH;
        float4* dst = (float4*)(dsts[m] + (size_t)n * HH * G4);
        int tx = tid & 31, ty = tid >> 5;
        #pragma unroll
        for (int g = 0; g < 4; g++)
            for (int jj = ty; jj < 32; jj += 8)
                st[g][jj][tx] = src[(g * HH + jt + jj) * HH + kt + tx];
        __syncthreads();
        for (int kk = ty; kk < 32; kk += 8) {
            float4 v;
            v.x = st[0][tx][kk]; v.y = st[1][tx][kk];
            v.z = st[2][tx][kk]; v.w = st[3][tx][kk];
            dst[(kt + kk) * HH + jt + tx] = v;
        }
    } else if (b < PREP_FCT_END) {
        // ---- fct: tiled transpose g_WfcT[n][k][r] = Wfc[n][r][k] ----
        float (*t)[33] = (float (*)[33])smb;
        int idx = b - PREP_TIK_END;
        int n  = idx >> 4;
        int yy = idx & 15;
        int tr = (yy >> 2) * 32;
        int tc = (yy & 3) * 32;
        const float* src = Wfc + (size_t)n * HH * HH;
        float* dst = g_WfcT + (size_t)n * HH * HH;
        int tx = tid & 31, ty = tid >> 5;
        #pragma unroll
        for (int i = ty; i < 32; i += 8)
            t[i][tx] = src[(tr + i) * HH + tc + tx];
        __syncthreads();
        #pragma unroll
        for (int i = ty; i < 32; i += 8)
            dst[(tc + i) * HH + tr + tx] = t[tx][i];
    } else if (b < PREP_GCN_END) {
        // ---- gcn: one timestep, dense-adjacency formulation ----
        float* A    = smb;
        float* B    = A + NN * HH;
        float* Adj  = B + NN * HH;
        float* dinv = Adj + NN * NN;
        int*   deg  = (int*)(dinv + NN);
        int*   rowS = deg + NN;
        int*   colS = rowS + EE;

        int t = b - PREP_FCT_END;
        const int* rowp = ei + (size_t)t * 2 * EE;
        const int* colp = rowp + EE;

        if (tid < NN) deg[tid] = 1;
        for (int i = tid; i < NN * NN; i += 256) Adj[i] = 0.0f;
        __syncthreads();
        for (int e = tid; e < EE; e += 256) {
            int r = rowp[e], c = colp[e];
            rowS[e] = r; colS[e] = c;
            atomicAdd(&deg[c], 1);
        }
        __syncthreads();
        if (tid < NN) dinv[tid] = rsqrtf((float)deg[tid]);
        __syncthreads();
        for (int e = tid; e < EE; e += 256) {
            int r = rowS[e], c = colS[e];
            atomicAdd(&Adj[c * NN + r], dinv[r] * dinv[c]);
        }
        if (tid < NN) atomicAdd(&Adj[tid * NN + tid], dinv[tid] * dinv[tid]);
        __syncthreads();

        const float* xt = x + (size_t)t * NN * INC;
        for (int o = tid; o < NN * HH; o += 256) {
            int r = o >> 7, c = o & 127;
            float s = 0.0f;
            #pragma unroll 8
            for (int k = 0; k < INC; k++) s += xt[r * INC + k] * W1[k * HH + c];
            A[o] = s;
        }
        __syncthreads();
        for (int o = tid; o < NN * HH; o += 256) {
            int cn = o >> 7, ch = o & 127;
            float s = 0.0f;
            #pragma unroll
            for (int r = 0; r < NN; r++) s += Adj[cn * NN + r] * A[r * HH + ch];
            B[o] = fmaxf(s + b1[ch], 0.0f);
        }
        __syncthreads();
        for (int o = tid; o < NN * HH; o += 256) {
            int r = o >> 7, c = o & 127;
            float s = 0.0f;
            #pragma unroll 8
            for (int k = 0; k < HH; k++) s += B[r * HH + k] * W2[k * HH + c];
            A[o] = s;
        }
        __syncthreads();
        for (int o = tid; o < NN * HH; o += 256) {
            int cn = o >> 7, ch = o & 127;
            float s = 0.0f;
            #pragma unroll
            for (int r = 0; r < NN; r++) s += Adj[cn * NN + r] * A[r * HH + ch];
            g_hgcn[((size_t)t * NN + cn) * HH + ch] = fmaxf(s + b2[ch], 0.0f);
        }
    } else {
        // ---- copy_y ----
        int i = (b - PREP_GCN_END) * 256 + tid;
        if (i < TT * NN * 4) ydst[i] = y[i];
    }
}

// ---------------- precompute P1[n][t][j][4] = Wih1[n] @ h_gcn[t][n] ----------------
// grid (NN, 8): 16 timesteps per block, 256 threads = (j, th in 0..1), 8 ts per thread
// as 4 f32x2 pairs. h staged transposed hs[k][ts] so each pair is one LDS.64 broadcast.
__global__ void __launch_bounds__(256) p1_kernel() {
    int n = blockIdx.x, tb = blockIdx.y * 16;
    __shared__ __align__(8) float hs[HH][HP];
    int tid = threadIdx.x;
    for (int i = tid; i < 16 * HH; i += 256) {
        int tt = i >> 7, k = i & 127;
        hs[k][tt] = g_hgcn[((size_t)(tb + tt) * NN + n) * HH + k];
    }
    __syncthreads();
    int j = tid & 127, th = tid >> 7;
    const float4* Wp = (const float4*)(g_WihTI1 + (size_t)n * HH * G4);

    unsigned long long acc[4][4];
    #pragma unroll
    for (int g = 0; g < 4; g++)
        #pragma unroll
        for (int p = 0; p < 4; p++) acc[g][p] = 0ull;

    float4 wvn = Wp[j];                           // prefetch k=0
    #pragma unroll 4
    for (int k = 0; k < HH; k++) {
        float4 wv = wvn;
        wvn = Wp[(((k + 1) & 127) << 7) + j];     // wraps harmlessly
        unsigned long long w0 = pk2(wv.x, wv.x), w1 = pk2(wv.y, wv.y);
        unsigned long long w2d = pk2(wv.z, wv.z), w3 = pk2(wv.w, wv.w);
        const unsigned long long* hp = (const unsigned long long*)&hs[k][th * 8];
        #pragma unroll
        for (int p = 0; p < 4; p++) {
            unsigned long long hv = hp[p];
            fma2(acc[0][p], w0, hv);
            fma2(acc[1][p], w1, hv);
            fma2(acc[2][p], w2d, hv);
            fma2(acc[3][p], w3, hv);
        }
    }

    float4* out = (float4*)(g_P1 + (size_t)n * TT * G4);
    #pragma unroll
    for (int p = 0; p < 4; p++) {
        float iA, iB, fA, fB, gA, gB, oA, oB;
        upk2(acc[0][p], iA, iB);
        upk2(acc[1][p], fA, fB);
        upk2(acc[2][p], gA, gB);
        upk2(acc[3][p], oA, oB);
        int tsA = tb + th * 8 + 2 * p;
        out[tsA * HH + j]       = make_float4(iA, fA, gA, oA);
        out[(tsA + 1) * HH + j] = make_float4(iB, fB, gB, oB);
    }
}

// ---------------- main 2-layer windowed LSTM + fc + heads (f32x2 packed) ----------------
// (UNCHANGED from the 779-us R14 version — at the RF-bank issue floor; do not touch.)
__global__ void __launch_bounds__(128) lstm_kernel(
    const float* __restrict__ bih1, const float* __restrict__ bhh1,
    const float* __restrict__ bih2, const float* __restrict__ bhh2,
    const float* __restrict__ bfc,
    const float* __restrict__ Wout0, const float* __restrict__ bout0,
    const float* __restrict__ Wout1, const float* __restrict__ bout1,
    float* __restrict__ dout)
{
    int n = blockIdx.x, chunk = blockIdx.y;
    int j = threadIdx.x;
    int tbase = chunk * SL;

    __shared__ __align__(16) float h1s[2][HH][HP];
    __shared__ __align__(16) float h2s[2][HH][HP];

    float c1[SL], c2[SL];
    #pragma unroll
    for (int w = 0; w < SL; w++) { c1[w] = 0.f; c2[w] = 0.f; }
    #pragma unroll
    for (int w2 = 0; w2 < 8; w2++) {
        ((unsigned long long*)h1s[0][j])[w2] = 0ull;
        ((unsigned long long*)h2s[0][j])[w2] = 0ull;
    }

    unsigned long long b1d[4], b2d[4];
    #pragma unroll
    for (int g = 0; g < 4; g++) {
        float v1 = bih1[n * G4 + g * HH + j] + bhh1[n * G4 + g * HH + j];
        float v2 = bih2[n * G4 + g * HH + j] + bhh2[n * G4 + g * HH + j];
        b1d[g] = pk2(v1, v1);
        b2d[g] = pk2(v2, v2);
    }

    const float4* Wh1 = (const float4*)(g_WhhTI1 + (size_t)n * HH * G4);
    const float4* Wi2 = (const float4*)(g_WihTI2 + (size_t)n * HH * G4);
    const float4* Wh2 = (const float4*)(g_WhhTI2 + (size_t)n * HH * G4);
    const float4* P1p = (const float4*)(g_P1     + (size_t)n * TT * G4);
    __syncthreads();

    for (int s = 0; s < SL; s++) {
        int rb = s & 1, wb = rb ^ 1;
        float (*h1R)[HP] = h1s[rb];
        float (*h1W)[HP] = h1s[wb];
        float (*h2R)[HP] = h2s[rb];
        float (*h2W)[HP] = h2s[wb];

        unsigned long long acc[4][8];
        #pragma unroll
        for (int g = 0; g < 4; g++)
            #pragma unroll
            for (int w2 = 0; w2 < 8; w2++) acc[g][w2] = b1d[g];

        float4 wvn = Wh1[j];
        #pragma unroll 4
        for (int k = 0; k < HH; k++) {
            float4 wv = wvn;
            wvn = Wh1[(((k + 1) & 127) << 7) + j];
            unsigned long long w0 = pk2(wv.x, wv.x), w1 = pk2(wv.y, wv.y);
            unsigned long long w2d = pk2(wv.z, wv.z), w3 = pk2(wv.w, wv.w);
            const unsigned long long* hp = (const unsigned long long*)h1R[k];
            #pragma unroll
            for (int w2 = 0; w2 < 8; w2++) {
                unsigned long long hv = hp[w2];
                fma2(acc[0][w2], w0, hv);
                fma2(acc[1][w2], w1, hv);
                fma2(acc[2][w2], w2d, hv);
                fma2(acc[3][w2], w3, hv);
            }
        }

        #pragma unroll
        for (int w2 = 0; w2 < 8; w2++) {
            float i0, i1, f0, f1, g0, g1, o0, o1;
            upk2(acc[0][w2], i0, i1);
            upk2(acc[1][w2], f0, f1);
            upk2(acc[2][w2], g0, g1);
            upk2(acc[3][w2], o0, o1);
            int wA = 2 * w2, wB = wA + 1;
            int tsA = tbase + wA - (SL - 1) + s;
            int tsB = tsA + 1;
            if (tsA >= 0) {
                float4 p = P1p[tsA * HH + j];
                i0 += p.x; f0 += p.y; g0 += p.z; o0 += p.w;
            }
            if (tsB >= 0) {
                float4 p = P1p[tsB * HH + j];
                i1 += p.x; f1 += p.y; g1 += p.z; o1 += p.w;
            }
            c1[wA] = sigf(f0) * c1[wA] + sigf(i0) * tanhfast(g0);
            float hA = sigf(o0) * tanhfast(c1[wA]);
            c1[wB] = sigf(f1) * c1[wB] + sigf(i1) * tanhfast(g1);
            float hB = sigf(o1) * tanhfast(c1[wB]);
            ((unsigned long long*)h1W[j])[w2] = pk2(hA, hB);
        }
        __syncthreads();

        #pragma unroll
        for (int g = 0; g < 4; g++)
            #pragma unroll
            for (int w2 = 0; w2 < 8; w2++) acc[g][w2] = b2d[g];

        float4 wivn = Wi2[j];
        float4 whvn = Wh2[j];
        #pragma unroll 2
        for (int k = 0; k < HH; k++) {
            float4 wiv = wivn;
            float4 whv = whvn;
            int kn = (((k + 1) & 127) << 7) + j;
            wivn = Wi2[kn];
            whvn = Wh2[kn];
            unsigned long long a0 = pk2(wiv.x, wiv.x), a1 = pk2(wiv.y, wiv.y);
            unsigned long long a2 = pk2(wiv.z, wiv.z), a3 = pk2(wiv.w, wiv.w);
            unsigned long long d0 = pk2(whv.x, whv.x), d1 = pk2(whv.y, whv.y);
            unsigned long long d2 = pk2(whv.z, whv.z), d3 = pk2(whv.w, whv.w);
            const unsigned long long* hp1 = (const unsigned long long*)h1W[k];
            const unsigned long long* hp2 = (const unsigned long long*)h2R[k];
            #pragma unroll
            for (int w2 = 0; w2 < 8; w2++) {
                unsigned long long hv1 = hp1[w2];
                unsigned long long hv2 = hp2[w2];
                fma2(acc[0][w2], a0, hv1); fma2(acc[0][w2], d0, hv2);
                fma2(acc[1][w2], a1, hv1); fma2(acc[1][w2], d1, hv2);
                fma2(acc[2][w2], a2, hv1); fma2(acc[2][w2], d2, hv2);
                fma2(acc[3][w2], a3, hv1); fma2(acc[3][w2], d3, hv2);
            }
        }

        #pragma unroll
        for (int w2 = 0; w2 < 8; w2++) {
            float i0, i1, f0, f1, g0, g1, o0, o1;
            upk2(acc[0][w2], i0, i1);
            upk2(acc[1][w2], f0, f1);
            upk2(acc[2][w2], g0, g1);
            upk2(acc[3][w2], o0, o1);
            int wA = 2 * w2, wB = wA + 1;
            c2[wA] = sigf(f0) * c2[wA] + sigf(i0) * tanhfast(g0);
            float hA = sigf(o0) * tanhfast(c2[wA]);
            c2[wB] = sigf(f1) * c2[wB] + sigf(i1) * tanhfast(g1);
            float hB = sigf(o1) * tanhfast(c2[wB]);
            ((unsigned long long*)h2W[j])[w2] = pk2(hA, hB);
        }
    }

    #pragma unroll
    for (int w = 0; w < SL; w++) h1s[0][j][w] = fmaxf(h2s[0][j][w], 0.0f);
    __syncthreads();

    {
        float bb = bfc[n * HH + j];
        unsigned long long fcv[8];
        unsigned long long bbd = pk2(bb, bb);
        #pragma unroll
        for (int w2 = 0; w2 < 8; w2++) fcv[w2] = bbd;
        const float* Wf = g_WfcT + (size_t)n * HH * HH;
        #pragma unroll 4
        for (int k = 0; k < HH; k++) {
            float wf = Wf[k * HH + j];
            unsigned long long wfd = pk2(wf, wf);
            const unsigned long long* hr = (const unsigned long long*)h1s[0][k];
            #pragma unroll
            for (int w2 = 0; w2 < 8; w2++) fma2(fcv[w2], wfd, hr[w2]);
        }
        __syncthreads();
        #pragma unroll
        for (int w2 = 0; w2 < 8; w2++)
            ((unsigned long long*)h2s[0][j])[w2] = fcv[w2];
        __syncthreads();
    }

    if (j < 96) {
        int w = j / 6, q = j % 6;
        const float* wr; float bo;
        if (q < 4) { wr = Wout0 + (size_t)(n * 4 + q) * HH;       bo = bout0[n * 4 + q]; }
        else       { wr = Wout1 + (size_t)(n * 2 + (q - 4)) * HH; bo = bout1[n * 2 + (q - 4)]; }
        float s2 = bo;
        #pragma unroll 8
        for (int k = 0; k < HH; k++) s2 += wr[k] * h2s[0][k][w];
        int t = tbase + w;
        if (q < 4) dout[((size_t)t * NN + n) * 4 + q] = s2;
        else       dout[(size_t)TT * NN * 4 + ((size_t)t * NN + n) * 2 + (q - 4)] = s2;
    }
}

// ---------------- launch ----------------
extern "C" void kernel_launch(void* const* d_in, const int* in_sizes, int n_in,
                              void* d_out, int out_size)
{
    const float* x     = (const float*)d_in[0];
    const int*   ei    = (const int*)  d_in[1];
    const float* y     = (const float*)d_in[3];
    const float* W1    = (const float*)d_in[4];
    const float* b1    = (const float*)d_in[5];
    const float* W2    = (const float*)d_in[6];
    const float* b2    = (const float*)d_in[7];
    const float* Wih1  = (const float*)d_in[8];
    const float* Whh1  = (const float*)d_in[9];
    const float* bih1  = (const float*)d_in[10];
    const float* bhh1  = (const float*)d_in[11];
    const float* Wih2  = (const float*)d_in[12];
    const float* Whh2  = (const float*)d_in[13];
    const float* bih2  = (const float*)d_in[14];
    const float* bhh2  = (const float*)d_in[15];
    const float* Wfc   = (const float*)d_in[16];
    const float* bfc   = (const float*)d_in[17];
    const float* Wout0 = (const float*)d_in[18];
    const float* bout0 = (const float*)d_in[19];
    const float* Wout1 = (const float*)d_in[20];
    const float* bout1 = (const float*)d_in[21];
    float* out = (float*)d_out;

    prep_kernel<<<PREP_NBLK, 256>>>(Wih1, Whh1, Wih2, Whh2, Wfc,
                                    x, ei, W1, b1, W2, b2,
                                    y, out + (size_t)TT * NN * 4 + (size_t)TT * NN * 2);
    p1_kernel<<<dim3(NN, 8), 256>>>();
    lstm_kernel<<<dim3(NN, TT / SL), HH>>>(bih1, bhh1, bih2, bhh2, bfc,
                                           Wout0, bout0, Wout1, bout1, out);
}

// round 17
// speedup vs baseline: 1.6390x; 1.0474x over previous
#include <cuda_runtime.h>

#define TT   128   // timesteps
#define NN   32    // nodes
#define EE   512   // edges per timestep
#define INC  64    // input channels
#define HH   128   // hidden
#define SL   16    // seq len / windows per block
#define G4   512   // 4*HH gates
#define HP   18    // padded h row stride (floats)

// ---------------- device scratch (static, no allocs) ----------------
__device__ float g_hgcn  [TT * NN * HH];   // [t][n][h]
__device__ float g_P1    [NN * TT * G4];   // [n][t][j][4]  (gate-interleaved)
__device__ float g_WihTI1[NN * HH * G4];   // [n][k][j][4]
__device__ float g_WhhTI1[NN * HH * G4];
__device__ float g_WihTI2[NN * HH * G4];
__device__ float g_WhhTI2[NN * HH * G4];
__device__ float g_WfcT  [NN * HH * HH];   // [n][k][r]

// ---------------- helpers ----------------
__device__ __forceinline__ float sigf(float x) {
    return __fdividef(1.0f, 1.0f + __expf(-x));
}
__device__ __forceinline__ float tanhfast(float x) {
    x = fminf(fmaxf(x, -15.0f), 15.0f);
    float e = __expf(2.0f * x);
    return __fdividef(e - 1.0f, e + 1.0f);
}
__device__ __forceinline__ unsigned long long pk2(float a, float b) {
    unsigned long long r;
    asm("mov.b64 %0,{%1,%2};" : "=l"(r) : "f"(a), "f"(b));
    return r;
}
__device__ __forceinline__ void upk2(unsigned long long v, float& a, float& b) {
    asm("mov.b64 {%0,%1},%2;" : "=f"(a), "=f"(b) : "l"(v));
}
__device__ __forceinline__ void fma2(unsigned long long& d, unsigned long long a, unsigned long long b) {
    asm("fma.rn.f32x2 %0,%1,%2,%0;" : "+l"(d) : "l"(a), "l"(b));
}

// ================ tik4 scatter transpose (NO smem, NO barriers) ================
// out[n][k][j*4+g] = in[n][g*128+j][k].  Thread (m,n,j,k): 4 coalesced LDGs (MLP=4),
// one STG.128 scatter (2x sector amplification only).
__global__ void __launch_bounds__(256) tik_scatter_kernel(
    const float* __restrict__ Wih1, const float* __restrict__ Whh1,
    const float* __restrict__ Wih2, const float* __restrict__ Whh2)
{
    int id = blockIdx.x * 256 + threadIdx.x;
    int k = id & 127;
    int j = (id >> 7) & 127;
    int n = (id >> 14) & 31;
    int m = id >> 19;
    const float* src = (m == 0) ? Wih1 : (m == 1) ? Whh1 : (m == 2) ? Wih2 : Whh2;
    float* dstf = (m == 0) ? g_WihTI1 : (m == 1) ? g_WhhTI1 : (m == 2) ? g_WihTI2 : g_WhhTI2;
    src += (size_t)n * G4 * HH;
    float4* dst = (float4*)(dstf + (size_t)n * HH * G4);
    float4 v;
    v.x = src[(0 * HH + j) * HH + k];
    v.y = src[(1 * HH + j) * HH + k];
    v.z = src[(2 * HH + j) * HH + k];
    v.w = src[(3 * HH + j) * HH + k];
    dst[k * HH + j] = v;
}

// ================ misc: fct + gcn + copy_y (smem-heavy branches, small grid) ====
#define MISC_FCT_END 512
#define MISC_GCN_END 640
#define MISC_NBLK    704
#define GCN_SMEM_FLOATS (NN*HH + NN*HH + NN*NN + NN + NN + EE + EE)  // 10304

__global__ void __launch_bounds__(256) misc_kernel(
    const float* __restrict__ Wfc,
    const float* __restrict__ x, const int* __restrict__ ei,
    const float* __restrict__ W1, const float* __restrict__ b1,
    const float* __restrict__ W2, const float* __restrict__ b2,
    const float* __restrict__ y, float* __restrict__ ydst)
{
    __shared__ __align__(16) float smb[GCN_SMEM_FLOATS];
    int b = blockIdx.x, tid = threadIdx.x;

    if (b < MISC_FCT_END) {
        // ---- fct: tiled transpose g_WfcT[n][k][r] = Wfc[n][r][k] ----
        float (*t)[33] = (float (*)[33])smb;
        int n  = b >> 4;
        int yy = b & 15;
        int tr = (yy >> 2) * 32;
        int tc = (yy & 3) * 32;
        const float* src = Wfc + (size_t)n * HH * HH;
        float* dst = g_WfcT + (size_t)n * HH * HH;
        int tx = tid & 31, ty = tid >> 5;
        #pragma unroll
        for (int i = ty; i < 32; i += 8)
            t[i][tx] = src[(tr + i) * HH + tc + tx];
        __syncthreads();
        #pragma unroll
        for (int i = ty; i < 32; i += 8)
            dst[(tc + i) * HH + tr + tx] = t[tx][i];
    } else if (b < MISC_GCN_END) {
        // ---- gcn: one timestep, dense-adjacency formulation ----
        float* A    = smb;
        float* B    = A + NN * HH;
        float* Adj  = B + NN * HH;
        float* dinv = Adj + NN * NN;
        int*   deg  = (int*)(dinv + NN);
        int*   rowS = deg + NN;
        int*   colS = rowS + EE;

        int t = b - MISC_FCT_END;
        const int* rowp = ei + (size_t)t * 2 * EE;
        const int* colp = rowp + EE;

        if (tid < NN) deg[tid] = 1;
        for (int i = tid; i < NN * NN; i += 256) Adj[i] = 0.0f;
        __syncthreads();
        for (int e = tid; e < EE; e += 256) {
            int r = rowp[e], c = colp[e];
            rowS[e] = r; colS[e] = c;
            atomicAdd(&deg[c], 1);
        }
        __syncthreads();
        if (tid < NN) dinv[tid] = rsqrtf((float)deg[tid]);
        __syncthreads();
        for (int e = tid; e < EE; e += 256) {
            int r = rowS[e], c = colS[e];
            atomicAdd(&Adj[c * NN + r], dinv[r] * dinv[c]);
        }
        if (tid < NN) atomicAdd(&Adj[tid * NN + tid], dinv[tid] * dinv[tid]);
        __syncthreads();

        const float* xt = x + (size_t)t * NN * INC;
        for (int o = tid; o < NN * HH; o += 256) {
            int r = o >> 7, c = o & 127;
            float s = 0.0f;
            #pragma unroll 8
            for (int k = 0; k < INC; k++) s += xt[r * INC + k] * W1[k * HH + c];
            A[o] = s;
        }
        __syncthreads();
        for (int o = tid; o < NN * HH; o += 256) {
            int cn = o >> 7, ch = o & 127;
            float s = 0.0f;
            #pragma unroll
            for (int r = 0; r < NN; r++) s += Adj[cn * NN + r] * A[r * HH + ch];
            B[o] = fmaxf(s + b1[ch], 0.0f);
        }
        __syncthreads();
        for (int o = tid; o < NN * HH; o += 256) {
            int r = o >> 7, c = o & 127;
            float s = 0.0f;
            #pragma unroll 8
            for (int k = 0; k < HH; k++) s += B[r * HH + k] * W2[k * HH + c];
            A[o] = s;
        }
        __syncthreads();
        for (int o = tid; o < NN * HH; o += 256) {
            int cn = o >> 7, ch = o & 127;
            float s = 0.0f;
            #pragma unroll
            for (int r = 0; r < NN; r++) s += Adj[cn * NN + r] * A[r * HH + ch];
            g_hgcn[((size_t)t * NN + cn) * HH + ch] = fmaxf(s + b2[ch], 0.0f);
        }
    } else {
        // ---- copy_y ----
        int i = (b - MISC_GCN_END) * 256 + tid;
        if (i < TT * NN * 4) ydst[i] = y[i];
    }
}

// ---------------- precompute P1[n][t][j][4] = Wih1[n] @ h_gcn[t][n] ----------------
// grid (NN, 8): 16 timesteps per block, f32x2 ts-pair packing, depth-1 prefetch.
__global__ void __launch_bounds__(256) p1_kernel() {
    int n = blockIdx.x, tb = blockIdx.y * 16;
    __shared__ __align__(8) float hs[HH][HP];
    int tid = threadIdx.x;
    for (int i = tid; i < 16 * HH; i += 256) {
        int tt = i >> 7, k = i & 127;
        hs[k][tt] = g_hgcn[((size_t)(tb + tt) * NN + n) * HH + k];
    }
    __syncthreads();
    int j = tid & 127, th = tid >> 7;
    const float4* Wp = (const float4*)(g_WihTI1 + (size_t)n * HH * G4);

    unsigned long long acc[4][4];
    #pragma unroll
    for (int g = 0; g < 4; g++)
        #pragma unroll
        for (int p = 0; p < 4; p++) acc[g][p] = 0ull;

    float4 wvn = Wp[j];
    #pragma unroll 4
    for (int k = 0; k < HH; k++) {
        float4 wv = wvn;
        wvn = Wp[(((k + 1) & 127) << 7) + j];
        unsigned long long w0 = pk2(wv.x, wv.x), w1 = pk2(wv.y, wv.y);
        unsigned long long w2d = pk2(wv.z, wv.z), w3 = pk2(wv.w, wv.w);
        const unsigned long long* hp = (const unsigned long long*)&hs[k][th * 8];
        #pragma unroll
        for (int p = 0; p < 4; p++) {
            unsigned long long hv = hp[p];
            fma2(acc[0][p], w0, hv);
            fma2(acc[1][p], w1, hv);
            fma2(acc[2][p], w2d, hv);
            fma2(acc[3][p], w3, hv);
        }
    }

    float4* out = (float4*)(g_P1 + (size_t)n * TT * G4);
    #pragma unroll
    for (int p = 0; p < 4; p++) {
        float iA, iB, fA, fB, gA, gB, oA, oB;
        upk2(acc[0][p], iA, iB);
        upk2(acc[1][p], fA, fB);
        upk2(acc[2][p], gA, gB);
        upk2(acc[3][p], oA, oB);
        int tsA = tb + th * 8 + 2 * p;
        out[tsA * HH + j]       = make_float4(iA, fA, gA, oA);
        out[(tsA + 1) * HH + j] = make_float4(iB, fB, gB, oB);
    }
}

// ---------------- main 2-layer windowed LSTM + fc + heads (f32x2 packed) ----------------
// (UNCHANGED — at the RF-bank issue floor; do not touch.)
__global__ void __launch_bounds__(128) lstm_kernel(
    const float* __restrict__ bih1, const float* __restrict__ bhh1,
    const float* __restrict__ bih2, const float* __restrict__ bhh2,
    const float* __restrict__ bfc,
    const float* __restrict__ Wout0, const float* __restrict__ bout0,
    const float* __restrict__ Wout1, const float* __restrict__ bout1,
    float* __restrict__ dout)
{
    int n = blockIdx.x, chunk = blockIdx.y;
    int j = threadIdx.x;
    int tbase = chunk * SL;

    __shared__ __align__(16) float h1s[2][HH][HP];
    __shared__ __align__(16) float h2s[2][HH][HP];

    float c1[SL], c2[SL];
    #pragma unroll
    for (int w = 0; w < SL; w++) { c1[w] = 0.f; c2[w] = 0.f; }
    #pragma unroll
    for (int w2 = 0; w2 < 8; w2++) {
        ((unsigned long long*)h1s[0][j])[w2] = 0ull;
        ((unsigned long long*)h2s[0][j])[w2] = 0ull;
    }

    unsigned long long b1d[4], b2d[4];
    #pragma unroll
    for (int g = 0; g < 4; g++) {
        float v1 = bih1[n * G4 + g * HH + j] + bhh1[n * G4 + g * HH + j];
        float v2 = bih2[n * G4 + g * HH + j] + bhh2[n * G4 + g * HH + j];
        b1d[g] = pk2(v1, v1);
        b2d[g] = pk2(v2, v2);
    }

    const float4* Wh1 = (const float4*)(g_WhhTI1 + (size_t)n * HH * G4);
    const float4* Wi2 = (const float4*)(g_WihTI2 + (size_t)n * HH * G4);
    const float4* Wh2 = (const float4*)(g_WhhTI2 + (size_t)n * HH * G4);
    const float4* P1p = (const float4*)(g_P1     + (size_t)n * TT * G4);
    __syncthreads();

    for (int s = 0; s < SL; s++) {
        int rb = s & 1, wb = rb ^ 1;
        float (*h1R)[HP] = h1s[rb];
        float (*h1W)[HP] = h1s[wb];
        float (*h2R)[HP] = h2s[rb];
        float (*h2W)[HP] = h2s[wb];

        unsigned long long acc[4][8];
        #pragma unroll
        for (int g = 0; g < 4; g++)
            #pragma unroll
            for (int w2 = 0; w2 < 8; w2++) acc[g][w2] = b1d[g];

        float4 wvn = Wh1[j];
        #pragma unroll 4
        for (int k = 0; k < HH; k++) {
            float4 wv = wvn;
            wvn = Wh1[(((k + 1) & 127) << 7) + j];
            unsigned long long w0 = pk2(wv.x, wv.x), w1 = pk2(wv.y, wv.y);
            unsigned long long w2d = pk2(wv.z, wv.z), w3 = pk2(wv.w, wv.w);
            const unsigned long long* hp = (const unsigned long long*)h1R[k];
            #pragma unroll
            for (int w2 = 0; w2 < 8; w2++) {
                unsigned long long hv = hp[w2];
                fma2(acc[0][w2], w0, hv);
                fma2(acc[1][w2], w1, hv);
                fma2(acc[2][w2], w2d, hv);
                fma2(acc[3][w2], w3, hv);
            }
        }

        #pragma unroll
        for (int w2 = 0; w2 < 8; w2++) {
            float i0, i1, f0, f1, g0, g1, o0, o1;
            upk2(acc[0][w2], i0, i1);
            upk2(acc[1][w2], f0, f1);
            upk2(acc[2][w2], g0, g1);
            upk2(acc[3][w2], o0, o1);
            int wA = 2 * w2, wB = wA + 1;
            int tsA = tbase + wA - (SL - 1) + s;
            int tsB = tsA + 1;
            if (tsA >= 0) {
                float4 p = P1p[tsA * HH + j];
                i0 += p.x; f0 += p.y; g0 += p.z; o0 += p.w;
            }
            if (tsB >= 0) {
                float4 p = P1p[tsB * HH + j];
                i1 += p.x; f1 += p.y; g1 += p.z; o1 += p.w;
            }
            c1[wA] = sigf(f0) * c1[wA] + sigf(i0) * tanhfast(g0);
            float hA = sigf(o0) * tanhfast(c1[wA]);
            c1[wB] = sigf(f1) * c1[wB] + sigf(i1) * tanhfast(g1);
            float hB = sigf(o1) * tanhfast(c1[wB]);
            ((unsigned long long*)h1W[j])[w2] = pk2(hA, hB);
        }
        __syncthreads();

        #pragma unroll
        for (int g = 0; g < 4; g++)
            #pragma unroll
            for (int w2 = 0; w2 < 8; w2++) acc[g][w2] = b2d[g];

        float4 wivn = Wi2[j];
        float4 whvn = Wh2[j];
        #pragma unroll 2
        for (int k = 0; k < HH; k++) {
            float4 wiv = wivn;
            float4 whv = whvn;
            int kn = (((k + 1) & 127) << 7) + j;
            wivn = Wi2[kn];
            whvn = Wh2[kn];
            unsigned long long a0 = pk2(wiv.x, wiv.x), a1 = pk2(wiv.y, wiv.y);
            unsigned long long a2 = pk2(wiv.z, wiv.z), a3 = pk2(wiv.w, wiv.w);
            unsigned long long d0 = pk2(whv.x, whv.x), d1 = pk2(whv.y, whv.y);
            unsigned long long d2 = pk2(whv.z, whv.z), d3 = pk2(whv.w, whv.w);
            const unsigned long long* hp1 = (const unsigned long long*)h1W[k];
            const unsigned long long* hp2 = (const unsigned long long*)h2R[k];
            #pragma unroll
            for (int w2 = 0; w2 < 8; w2++) {
                unsigned long long hv1 = hp1[w2];
                unsigned long long hv2 = hp2[w2];
                fma2(acc[0][w2], a0, hv1); fma2(acc[0][w2], d0, hv2);
                fma2(acc[1][w2], a1, hv1); fma2(acc[1][w2], d1, hv2);
                fma2(acc[2][w2], a2, hv1); fma2(acc[2][w2], d2, hv2);
                fma2(acc[3][w2], a3, hv1); fma2(acc[3][w2], d3, hv2);
            }
        }

        #pragma unroll
        for (int w2 = 0; w2 < 8; w2++) {
            float i0, i1, f0, f1, g0, g1, o0, o1;
            upk2(acc[0][w2], i0, i1);
            upk2(acc[1][w2], f0, f1);
            upk2(acc[2][w2], g0, g1);
            upk2(acc[3][w2], o0, o1);
            int wA = 2 * w2, wB = wA + 1;
            c2[wA] = sigf(f0) * c2[wA] + sigf(i0) * tanhfast(g0);
            float hA = sigf(o0) * tanhfast(c2[wA]);
            c2[wB] = sigf(f1) * c2[wB] + sigf(i1) * tanhfast(g1);
            float hB = sigf(o1) * tanhfast(c2[wB]);
            ((unsigned long long*)h2W[j])[w2] = pk2(hA, hB);
        }
    }

    #pragma unroll
    for (int w = 0; w < SL; w++) h1s[0][j][w] = fmaxf(h2s[0][j][w], 0.0f);
    __syncthreads();

    {
        float bb = bfc[n * HH + j];
        unsigned long long fcv[8];
        unsigned long long bbd = pk2(bb, bb);
        #pragma unroll
        for (int w2 = 0; w2 < 8; w2++) fcv[w2] = bbd;
        const float* Wf = g_WfcT + (size_t)n * HH * HH;
        #pragma unroll 4
        for (int k = 0; k < HH; k++) {
            float wf = Wf[k * HH + j];
            unsigned long long wfd = pk2(wf, wf);
            const unsigned long long* hr = (const unsigned long long*)h1s[0][k];
            #pragma unroll
            for (int w2 = 0; w2 < 8; w2++) fma2(fcv[w2], wfd, hr[w2]);
        }
        __syncthreads();
        #pragma unroll
        for (int w2 = 0; w2 < 8; w2++)
            ((unsigned long long*)h2s[0][j])[w2] = fcv[w2];
        __syncthreads();
    }

    if (j < 96) {
        int w = j / 6, q = j % 6;
        const float* wr; float bo;
        if (q < 4) { wr = Wout0 + (size_t)(n * 4 + q) * HH;       bo = bout0[n * 4 + q]; }
        else       { wr = Wout1 + (size_t)(n * 2 + (q - 4)) * HH; bo = bout1[n * 2 + (q - 4)]; }
        float s2 = bo;
        #pragma unroll 8
        for (int k = 0; k < HH; k++) s2 += wr[k] * h2s[0][k][w];
        int t = tbase + w;
        if (q < 4) dout[((size_t)t * NN + n) * 4 + q] = s2;
        else       dout[(size_t)TT * NN * 4 + ((size_t)t * NN + n) * 2 + (q - 4)] = s2;
    }
}

// ---------------- launch ----------------
extern "C" void kernel_launch(void* const* d_in, const int* in_sizes, int n_in,
                              void* d_out, int out_size)
{
    const float* x     = (const float*)d_in[0];
    const int*   ei    = (const int*)  d_in[1];
    const float* y     = (const float*)d_in[3];
    const float* W1    = (const float*)d_in[4];
    const float* b1    = (const float*)d_in[5];
    const float* W2    = (const float*)d_in[6];
    const float* b2    = (const float*)d_in[7];
    const float* Wih1  = (const float*)d_in[8];
    const float* Whh1  = (const float*)d_in[9];
    const float* bih1  = (const float*)d_in[10];
    const float* bhh1  = (const float*)d_in[11];
    const float* Wih2  = (const float*)d_in[12];
    const float* Whh2  = (const float*)d_in[13];
    const float* bih2  = (const float*)d_in[14];
    const float* bhh2  = (const float*)d_in[15];
    const float* Wfc   = (const float*)d_in[16];
    const float* bfc   = (const float*)d_in[17];
    const float* Wout0 = (const float*)d_in[18];
    const float* bout0 = (const float*)d_in[19];
    const float* Wout1 = (const float*)d_in[20];
    const float* bout1 = (const float*)d_in[21];
    float* out = (float*)d_out;

    tik_scatter_kernel<<<4 * NN * HH * HH / 256, 256>>>(Wih1, Whh1, Wih2, Whh2);
    misc_kernel<<<MISC_NBLK, 256>>>(Wfc, x, ei, W1, b1, W2, b2,
                                    y, out + (size_t)TT * NN * 4 + (size_t)TT * NN * 2);
    p1_kernel<<<dim3(NN, 8), 256>>>();
    lstm_kernel<<<dim3(NN, TT / SL), HH>>>(bih1, bhh1, bih2, bhh2, bfc,
                                           Wout0, bout0, Wout1, bout1, out);
}